// round 16
// baseline (speedup 1.0000x reference)
#include <cuda_runtime.h>
#include <cstdint>

// Problem shape (fixed by reference setup_inputs)
#define B_ 8
#define C_ 128
#define H_ 256
#define W_ 256
#define N_ (H_ * W_)     // 65536 pixels per image
#define S_ 1024          // segments per image
#define PLANE4 (N_ / 4)  // plane stride in float4 units = 16384

#define ACC_ELEMS (B_ * S_ * C_)      // 1M floats per replica
#define F4_TOTAL (ACC_ELEMS / 4)      // 262144 float4 per replica

// TWO accumulator replicas (measured best): scatter CTAs alternate by chunk
// parity. Zero at static init; finalize re-zeroes both (and g_counts),
// preserving the zero-at-entry invariant across graph replays.
__device__ float g_accum0[ACC_ELEMS];
__device__ float g_accum1[ACC_ELEMS];
__device__ float g_counts[B_ * S_];

// ---------------------------------------------------------------------------
// Scatter + fused count.  grid: (16 chunks, C_/8 cg-PAIRS, B_), block 256.
// Labels are read once per 8 channels (halves label LTS traffic vs the
// quad-grid version: 64 MB -> 32 MB). To avoid R10's register blowup (60
// regs, occ 43%), the two channel-quads of the pair are processed
// SEQUENTIALLY per pixel-group: only 4 float4s live at once.
// Per thread, per group of 4 consecutive pixels:
//   1x LDG.128 labels, then 2 x { 4x LDG.128 planes + 4x red.v4 }.
// Replica = chunk & 1. cgp==0 blocks also histogram labels into g_counts.
// ---------------------------------------------------------------------------
__global__ void __launch_bounds__(256) scatter_kernel(
    const float* __restrict__ in,
    const int* __restrict__ labels)
{
    __shared__ int hist[S_];

    const int b     = blockIdx.z;
    const int cgp   = blockIdx.y;    // channel-group pair (8 channels)
    const int chunk = blockIdx.x;    // 4096-pixel spatial chunk
    const int t     = threadIdx.x;
    const bool do_count = (cgp == 0);   // uniform per block

    if (do_count) {
        for (int i = t; i < S_; i += 256) hist[i] = 0;
        __syncthreads();
    }

    const float4* p0 = reinterpret_cast<const float4*>(
                           in + ((size_t)b * C_ + (size_t)cgp * 8) * N_)
                       + chunk * 1024;
    const int4* lab4 = reinterpret_cast<const int4*>(
                           labels + (size_t)b * N_ + chunk * 4096);
    float* const rep = (chunk & 1) ? g_accum1 : g_accum0;
    float* const ob  = rep + (size_t)b * S_ * C_ + cgp * 8;

    #pragma unroll
    for (int g = 0; g < 4; g++) {
        const int idx = g * 256 + t;               // float4 index within chunk
        const int4 sg = lab4[idx];

        if (do_count) {
            atomicAdd(&hist[sg.x], 1);
            atomicAdd(&hist[sg.y], 1);
            atomicAdd(&hist[sg.z], 1);
            atomicAdd(&hist[sg.w], 1);
        }

        // 32-bit row offsets, reused by both quads
        const int r0 = sg.x * C_;
        const int r1 = sg.y * C_;
        const int r2 = sg.z * C_;
        const int r3 = sg.w * C_;

        {   // quad 0: channels cgp*8 .. +3
            const float4 x0 = p0[idx];
            const float4 x1 = p0[PLANE4     + idx];
            const float4 x2 = p0[2 * PLANE4 + idx];
            const float4 x3 = p0[3 * PLANE4 + idx];
            asm volatile("red.global.add.v4.f32 [%0], {%1, %2, %3, %4};"
                         :: "l"(ob + r0), "f"(x0.x), "f"(x1.x), "f"(x2.x), "f"(x3.x) : "memory");
            asm volatile("red.global.add.v4.f32 [%0], {%1, %2, %3, %4};"
                         :: "l"(ob + r1), "f"(x0.y), "f"(x1.y), "f"(x2.y), "f"(x3.y) : "memory");
            asm volatile("red.global.add.v4.f32 [%0], {%1, %2, %3, %4};"
                         :: "l"(ob + r2), "f"(x0.z), "f"(x1.z), "f"(x2.z), "f"(x3.z) : "memory");
            asm volatile("red.global.add.v4.f32 [%0], {%1, %2, %3, %4};"
                         :: "l"(ob + r3), "f"(x0.w), "f"(x1.w), "f"(x2.w), "f"(x3.w) : "memory");
        }
        {   // quad 1: channels cgp*8+4 .. +7
            const float4 x0 = p0[4 * PLANE4 + idx];
            const float4 x1 = p0[5 * PLANE4 + idx];
            const float4 x2 = p0[6 * PLANE4 + idx];
            const float4 x3 = p0[7 * PLANE4 + idx];
            asm volatile("red.global.add.v4.f32 [%0], {%1, %2, %3, %4};"
                         :: "l"(ob + r0 + 4), "f"(x0.x), "f"(x1.x), "f"(x2.x), "f"(x3.x) : "memory");
            asm volatile("red.global.add.v4.f32 [%0], {%1, %2, %3, %4};"
                         :: "l"(ob + r1 + 4), "f"(x0.y), "f"(x1.y), "f"(x2.y), "f"(x3.y) : "memory");
            asm volatile("red.global.add.v4.f32 [%0], {%1, %2, %3, %4};"
                         :: "l"(ob + r2 + 4), "f"(x0.z), "f"(x1.z), "f"(x2.z), "f"(x3.z) : "memory");
            asm volatile("red.global.add.v4.f32 [%0], {%1, %2, %3, %4};"
                         :: "l"(ob + r3 + 4), "f"(x0.w), "f"(x1.w), "f"(x2.w), "f"(x3.w) : "memory");
        }
    }

    if (do_count) {
        __syncthreads();
        for (int i = t; i < S_; i += 256) {
            int v = hist[i];
            if (v) atomicAdd(&g_counts[b * S_ + i], (float)v);
        }
    }
}

// ---------------------------------------------------------------------------
// Finalize: out = (acc0+acc1) / max(cnt,1); zero acc0, acc1, counts.
// grid 1024 x block 256, one float4 per thread. Warp w's 32 lanes are the
// only readers of count word gt>>5, so lane 0 zeroes it after __syncwarp().
// ---------------------------------------------------------------------------
__global__ void __launch_bounds__(256) finalize_kernel(float4* __restrict__ out) {
    const int gt = blockIdx.x * blockDim.x + threadIdx.x;   // 0..F4_TOTAL-1
    float4* acc0 = reinterpret_cast<float4*>(g_accum0);
    float4* acc1 = reinterpret_cast<float4*>(g_accum1);

    const float cnt = g_counts[gt >> 5];
    const float4 u = acc0[gt];
    const float4 w = acc1[gt];

    __syncwarp();
    if ((threadIdx.x & 31) == 0) g_counts[gt >> 5] = 0.0f;

    const float s = 1.0f / fmaxf(cnt, 1.0f);
    float4 v;
    v.x = (u.x + w.x) * s;
    v.y = (u.y + w.y) * s;
    v.z = (u.z + w.z) * s;
    v.w = (u.w + w.w) * s;
    out[gt] = v;
    const float4 z = make_float4(0.f, 0.f, 0.f, 0.f);
    acc0[gt] = z;                       // restore zero invariant
    acc1[gt] = z;
}

// ---------------------------------------------------------------------------
// kernel_launch: scatter -> finalize.  2 launches, graph-capturable.
// ---------------------------------------------------------------------------
extern "C" void kernel_launch(void* const* d_in, const int* in_sizes, int n_in,
                              void* d_out, int out_size) {
    const float* in     = (const float*)d_in[0];
    const int*   labels = (const int*)d_in[1];

    scatter_kernel<<<dim3(16, C_ / 8, B_), 256>>>(in, labels);

    finalize_kernel<<<F4_TOTAL / 256, 256>>>((float4*)d_out);
}